// round 16
// baseline (speedup 1.0000x reference)
#include <cuda_runtime.h>
#include <cuda_fp16.h>
#include <cstdint>
#include <cstddef>

#define BB  8
#define TT  4096
#define CC  1024
#define HSS 128
#define M_TOT (BB*TT)
#define QSTR 136   // attn strides (halves)
#define KSTR 136
#define VSTR 72
#define XS2  72    // qkv tile stride (halves), K-chunk 64

typedef unsigned long long u64;
typedef uint32_t u32;

__device__ __half g_q [BB*TT*HSS];
__device__ __half g_k [BB*TT*HSS];
__device__ __half g_vt[BB*HSS*TT];      // V transposed [b][d][t]
__device__ __half g_xh[M_TOT*CC];       // X (fp16)
__device__ __half g_wt[3*HSS*CC];       // W transposed; Wq pre-scaled by HS^-.5*log2e

// ---------------- helpers ----------------
__device__ __forceinline__ u32 pk2h(float lo, float hi){
    u32 r; asm("cvt.rn.f16x2.f32 %0, %1, %2;" : "=r"(r) : "f"(hi), "f"(lo)); return r;
}
__device__ __forceinline__ float ex2(float x){
    float r; asm("ex2.approx.f32 %0, %1;" : "=f"(r) : "f"(x)); return r;
}
__device__ __forceinline__ void mma16(float* d, const u32* a, u32 b0, u32 b1){
    asm volatile("mma.sync.aligned.m16n8k16.row.col.f32.f16.f16.f32 "
        "{%0,%1,%2,%3}, {%4,%5,%6,%7}, {%8,%9}, {%0,%1,%2,%3};"
        : "+f"(d[0]), "+f"(d[1]), "+f"(d[2]), "+f"(d[3])
        : "r"(a[0]), "r"(a[1]), "r"(a[2]), "r"(a[3]), "r"(b0), "r"(b1));
}
__device__ __forceinline__ void ldsm4(u32* r, u32 addr){
    asm volatile("ldmatrix.sync.aligned.m8n8.x4.shared.b16 {%0,%1,%2,%3}, [%4];"
        : "=r"(r[0]), "=r"(r[1]), "=r"(r[2]), "=r"(r[3]) : "r"(addr));
}
__device__ __forceinline__ u32 s2u(const void* p){
    u32 a; asm("{ .reg .u64 t; cvta.to.shared.u64 t, %1; cvt.u32.u64 %0, t; }" : "=r"(a) : "l"(p));
    return a;
}
__device__ __forceinline__ void cpa16(u32 dst, const void* src){
    asm volatile("cp.async.cg.shared.global [%0], [%1], 16;" :: "r"(dst), "l"(src) : "memory");
}
#define CP_COMMIT() asm volatile("cp.async.commit_group;" ::: "memory")
#define CP_WAIT0()  asm volatile("cp.async.wait_group 0;" ::: "memory")

// ---------------------------------------------------------------------------
// Fused prep: X -> fp16, W -> fp16 transposed (Wq pre-scaled by HS^-.5*log2e).
// ---------------------------------------------------------------------------
#define NXB (M_TOT*CC/2048)
#define NWB (3*HSS*CC/256)
__global__ __launch_bounds__(256)
void prep_kernel(const float* __restrict__ x,
                 const float* __restrict__ Wq,
                 const float* __restrict__ Wk,
                 const float* __restrict__ Wv)
{
    if (blockIdx.x < NXB) {
        const size_t i0 = ((size_t)blockIdx.x * 256 + threadIdx.x) * 8;
        float4 v0 = *(const float4*)(x + i0);
        float4 v1 = *(const float4*)(x + i0 + 4);
        uint4 u;
        u.x = pk2h(v0.x, v0.y);
        u.y = pk2h(v0.z, v0.w);
        u.z = pk2h(v1.x, v1.y);
        u.w = pk2h(v1.z, v1.w);
        *(uint4*)(g_xh + i0) = u;
    } else {
        const int idx = (blockIdx.x - NXB) * 256 + threadIdx.x;
        const int which = idx >> 17;
        const int rem   = idx & 131071;
        const int n = rem >> 10, k = rem & 1023;
        const float* W = (which==0) ? Wq : (which==1) ? Wk : Wv;
        float v = W[(size_t)k*HSS + n];
        if (which == 0) v *= 0.12751879523595898f;   // HS^-0.5 * log2(e)
        g_wt[(size_t)which*HSS*CC + (size_t)n*CC + k] = __float2half_rn(v);
    }
}

// ---------------------------------------------------------------------------
// QKV projection — unchanged (K-chunk 64, at fp16 tensor roofline).
// ---------------------------------------------------------------------------
__global__ __launch_bounds__(256, 2)
void qkv_mma_kernel()
{
    extern __shared__ __half qsm[];
    const int which = blockIdx.y;
    const __half* __restrict__ wt = g_wt + (size_t)which*HSS*CC;

    const int m0  = blockIdx.x * 128;
    const int tid = threadIdx.x;
    const int wid  = tid >> 5;
    const int lane = tid & 31;
    const int wm = wid >> 1, wn = wid & 1;
    const int g = lane >> 2, t = lane & 3;
    const int l8 = lane & 7;
    const int m0b = 32*wm;
    const int nb  = 64*wn;

    const u32 sbase = s2u(qsm);
    const u32 a_ln = 2u*(u32)((m0b + ((lane>>3)&1)*8 + l8)*XS2 + (lane>>4)*8);
    const u32 b_ln = 2u*(u32)((nb  + (lane>>4)*8 + l8)*XS2 + ((lane>>3)&1)*8);

    float o[2][8][4];
    #pragma unroll
    for (int i = 0; i < 2; i++)
        #pragma unroll
        for (int j = 0; j < 8; j++)
            #pragma unroll
            for (int q = 0; q < 4; q++) o[i][j][q] = 0.f;

    {
        #pragma unroll
        for (int l = 0; l < 4; l++) {
            int f = tid + (l<<8);
            int row = f >> 3, c = f & 7;
            u32 doff = 2u*(u32)(row*XS2 + c*8);
            cpa16(sbase + doff,           g_xh + (size_t)(m0+row)*CC + c*8);
            cpa16(sbase + 2u*9216 + doff, wt + (size_t)row*CC + c*8);
        }
        CP_COMMIT();
    }

    for (int ic = 0; ic < 16; ic++) {
        const int buf = ic & 1;
        CP_WAIT0();
        __syncthreads();
        if (ic < 15) {
            const int k0n = (ic+1) << 6;
            const u32 db = sbase + 2u*(u32)((buf^1)*18432);
            #pragma unroll
            for (int l = 0; l < 4; l++) {
                int f = tid + (l<<8);
                int row = f >> 3, c = f & 7;
                u32 doff = 2u*(u32)(row*XS2 + c*8);
                cpa16(db + doff,           g_xh + (size_t)(m0+row)*CC + k0n + c*8);
                cpa16(db + 2u*9216 + doff, wt + (size_t)row*CC + k0n + c*8);
            }
            CP_COMMIT();
        }

        const u32 bo = sbase + 2u*(u32)(buf*18432);
        const u32 xh_a = bo + a_ln;
        const u32 wt_b = bo + 2u*9216 + b_ln;

        #pragma unroll
        for (int kk = 0; kk < 4; kk++) {
            const u32 koff = (u32)(kk << 5);
            u32 ah[2][4];
            ldsm4(ah[0], xh_a + koff);
            ldsm4(ah[1], xh_a + (u32)(16*XS2*2) + koff);
            #pragma unroll
            for (int jp = 0; jp < 4; jp++) {
                u32 bw[4];
                ldsm4(bw, wt_b + (u32)(jp*(16*XS2*2)) + koff);
                mma16(o[0][2*jp],   ah[0], bw[0], bw[1]);
                mma16(o[0][2*jp+1], ah[0], bw[2], bw[3]);
                mma16(o[1][2*jp],   ah[1], bw[0], bw[1]);
                mma16(o[1][2*jp+1], ah[1], bw[2], bw[3]);
            }
        }
    }

    if (which != 2) {
        __half* __restrict__ outh = (which==0) ? g_q : g_k;
        #pragma unroll
        for (int mb = 0; mb < 2; mb++)
            #pragma unroll
            for (int h = 0; h < 2; h++) {
                const int row = m0 + m0b + 16*mb + 8*h + g;
                #pragma unroll
                for (int j = 0; j < 8; j++) {
                    u32 p = pk2h(o[mb][j][2*h+0], o[mb][j][2*h+1]);
                    *(u32*)(outh + (size_t)row*HSS + nb + 8*j + 2*t) = p;
                }
            }
    } else {
        __syncthreads();
        float* ts = (float*)qsm;
        #pragma unroll
        for (int mb = 0; mb < 2; mb++)
            #pragma unroll
            for (int h = 0; h < 2; h++) {
                const int r = m0b + 16*mb + 8*h + g;
                #pragma unroll
                for (int j = 0; j < 8; j++) {
                    const int c = nb + 8*j + 2*t;
                    ts[c*132 + r]     = o[mb][j][2*h+0];
                    ts[(c+1)*132 + r] = o[mb][j][2*h+1];
                }
            }
        __syncthreads();
        const int bb = m0 >> 12;
        const int t0 = m0 & (TT-1);
        __half* __restrict__ vt = g_vt + (size_t)bb*HSS*TT;
        #pragma unroll
        for (int l = 0; l < 16; l++) {
            int f = tid + (l<<8);
            int d = f >> 5, c4 = f & 31;
            const float* src = &ts[d*132 + (c4<<2)];
            uint2 u;
            u.x = pk2h(src[0], src[1]);
            u.y = pk2h(src[2], src[3]);
            *(uint2*)(vt + (size_t)d*TT + t0 + (c4<<2)) = u;
        }
    }
}

// ---------------------------------------------------------------------------
// fp16 banded attention (R14 structure, proven): BM=64, 4 warps, 2 CTAs/SM,
// warp-level band skip + NEW 16-col slice-level skip on boundary tiles.
// smem halves: Q@0 (64x136)  K0@8704 K1@17408  V0@26112 V1@35328.  89088 B.
// ---------------------------------------------------------------------------
__global__ __launch_bounds__(128, 2)
void attn_mma_kernel(float* __restrict__ out)
{
    extern __shared__ __half hsm[];

    const int tid  = threadIdx.x;
    const int wid  = tid >> 5;
    const int lane = tid & 31;
    const int g = lane >> 2, t = lane & 3;
    const int l8 = lane & 7;
    const int m0b = 16*wid;

    const int b  = blockIdx.x & 7;
    const int qt = 63 - (blockIdx.x >> 3);
    const int r0 = qt << 6;

    const u32 sbase = s2u(hsm);
    const u32 qa = sbase + 2u*(u32)((m0b + ((lane>>3)&1)*8 + l8)*QSTR + (lane>>4)*8);
    const u32 k_ln = 2u*(u32)((((lane>>4)*8) + l8)*KSTR + ((lane>>3)&1)*8);
    const u32 v_ln = 2u*(u32)((((lane>>4)*8) + l8)*VSTR + ((lane>>3)&1)*8);

    const __half* __restrict__ kbase  = g_k  + (size_t)b*TT*HSS;
    const __half* __restrict__ vtbase = g_vt + (size_t)b*HSS*TT;
    const __half* __restrict__ qb     = g_q  + ((size_t)b*TT + r0)*HSS;

    const int rmax = r0 + 63;
    const int ct0 = (2047 - (rmax>>1)) >> 6;
    const int ct1 = (2047 + ((rmax+1)>>1)) >> 6;

    // prologue: Q + first K + first V^T
    {
        #pragma unroll
        for (int l = 0; l < 8; l++) {
            int f = tid + (l<<7);
            int row = f >> 4, c16 = f & 15;
            cpa16(sbase + 2u*(u32)(row*QSTR + (c16<<3)), qb + row*HSS + (c16<<3));
        }
        const int c0 = ct0 << 6;
        const __half* kb = kbase + (size_t)c0*HSS;
        #pragma unroll
        for (int l = 0; l < 8; l++) {
            int f = tid + (l<<7);
            int row = f >> 4, c16 = f & 15;
            cpa16(sbase + 2u*(u32)(8704 + row*KSTR + (c16<<3)), kb + row*HSS + (c16<<3));
        }
        #pragma unroll
        for (int l = 0; l < 8; l++) {
            int f = tid + (l<<7);
            int row = f >> 3, c8 = f & 7;
            cpa16(sbase + 2u*(u32)(26112 + row*VSTR + (c8<<3)),
                  vtbase + (size_t)row*TT + c0 + (c8<<3));
        }
        CP_COMMIT();
    }

    const int grA = r0 + m0b + g, grB = grA + 8;
    const int loA = 2047 - (grA >> 1), hiA = 2047 + ((grA + 1) >> 1);
    const int loB = 2047 - (grB >> 1), hiB = 2047 + ((grB + 1) >> 1);
    const int rwn = r0 + m0b;
    const int loWn = 2047 - (rwn >> 1), hiWn = 2047 + ((rwn + 1) >> 1);
    const int rww = r0 + m0b + 15;
    const int loWw = 2047 - (rww >> 1), hiWw = 2047 + ((rww + 1) >> 1);

    float o[16][4];
    #pragma unroll
    for (int j = 0; j < 16; j++)
        #pragma unroll
        for (int q = 0; q < 4; q++) o[j][q] = 0.f;
    float lA = 0.f, lB = 0.f;

    int buf = 0;
    for (int ct = ct0; ct <= ct1; ct++, buf ^= 1) {
        CP_WAIT0();
        __syncthreads();

        if (ct < ct1) {
            const int c0n = (ct+1) << 6;
            const __half* kb = kbase + (size_t)c0n*HSS;
            const u32 kd = sbase + 2u*(u32)(8704 + (buf^1)*8704);
            const u32 vd = sbase + 2u*(u32)(26112 + (buf^1)*9216);
            #pragma unroll
            for (int l = 0; l < 8; l++) {
                int f = tid + (l<<7);
                int row = f >> 4, c16 = f & 15;
                cpa16(kd + 2u*(u32)(row*KSTR + (c16<<3)), kb + row*HSS + (c16<<3));
            }
            #pragma unroll
            for (int l = 0; l < 8; l++) {
                int f = tid + (l<<7);
                int row = f >> 3, c8 = f & 7;
                cpa16(vd + 2u*(u32)(row*VSTR + (c8<<3)),
                      vtbase + (size_t)row*TT + c0n + (c8<<3));
            }
            CP_COMMIT();
        }

        const int c0 = ct << 6;
        if (c0 + 63 < loWw || c0 > hiWw) continue;   // warp-level band skip

        // 16-col slice activity (warp-uniform): slice jp covers [c0+16jp, c0+16jp+15]
        bool act[4];
        #pragma unroll
        for (int jp = 0; jp < 4; jp++) {
            const int cs = c0 + 16*jp;
            act[jp] = !(cs + 15 < loWw || cs > hiWw);
        }

        const u32 kbuf = sbase + 2u*(u32)(8704 + buf*8704) + k_ln;
        const u32 vbuf = sbase + 2u*(u32)(26112 + buf*9216) + v_ln;

        // ---- MMA1: S(16x64 per warp) = Q @ K^T  (skip inactive slices) ----
        float s[8][4];
        #pragma unroll
        for (int j = 0; j < 8; j++)
            #pragma unroll
            for (int q = 0; q < 4; q++) s[j][q] = 0.f;

        #pragma unroll
        for (int kk = 0; kk < 8; kk++) {
            u32 a[4];
            ldsm4(a, qa + (u32)(kk<<5));
            #pragma unroll
            for (int jp = 0; jp < 4; jp++) {
                if (!act[jp]) continue;
                u32 bk[4];
                ldsm4(bk, kbuf + (u32)(jp*(16*KSTR*2)) + (u32)(kk<<5));
                mma16(s[2*jp],   a, bk[0], bk[1]);
                mma16(s[2*jp+1], a, bk[2], bk[3]);
            }
        }

        // ---- mask (boundary tiles only) ----
        if (c0 < loWn || c0 + 63 > hiWn) {
            #pragma unroll
            for (int jb = 0; jb < 8; jb++) {
                const int cb = c0 + 8*jb + 2*t;
                if (cb   < loA || cb   > hiA) s[jb][0] = -1e30f;
                if (cb+1 < loA || cb+1 > hiA) s[jb][1] = -1e30f;
                if (cb   < loB || cb   > hiB) s[jb][2] = -1e30f;
                if (cb+1 < loB || cb+1 > hiB) s[jb][3] = -1e30f;
            }
        }

        // ---- fused exp (2^S) + MMA2 per 16-col k-slice (skip inactive) ----
        #pragma unroll
        for (int jk = 0; jk < 4; jk++) {
            if (!act[jk]) continue;
            u32 aP[4];
            #pragma unroll
            for (int h = 0; h < 2; h++) {
                const int jb = 2*jk + h;
                float p0 = ex2(s[jb][0]);
                float p1 = ex2(s[jb][1]);
                float p2 = ex2(s[jb][2]);
                float p3 = ex2(s[jb][3]);
                lA += p0 + p1;
                lB += p2 + p3;
                aP[2*h+0] = pk2h(p0, p1);
                aP[2*h+1] = pk2h(p2, p3);
            }
            #pragma unroll
            for (int jp = 0; jp < 8; jp++) {
                u32 bv[4];
                ldsm4(bv, vbuf + (u32)(jp*(16*VSTR*2)) + (u32)(jk<<5));
                mma16(o[2*jp],   aP, bv[0], bv[1]);
                mma16(o[2*jp+1], aP, bv[2], bv[3]);
            }
        }
    }

    // ---- epilogue ----
    lA += __shfl_xor_sync(0xffffffffu, lA, 1);
    lA += __shfl_xor_sync(0xffffffffu, lA, 2);
    lB += __shfl_xor_sync(0xffffffffu, lB, 1);
    lB += __shfl_xor_sync(0xffffffffu, lB, 2);
    const float invA = 1.0f / lA;
    const float invB = 1.0f / lB;

    float* __restrict__ obA = out + ((size_t)b*TT + grA)*HSS;
    float* __restrict__ obB = out + ((size_t)b*TT + grB)*HSS;
    #pragma unroll
    for (int jb = 0; jb < 16; jb++) {
        *(float2*)&obA[8*jb + 2*t] = make_float2(o[jb][0]*invA, o[jb][1]*invA);
        *(float2*)&obB[8*jb + 2*t] = make_float2(o[jb][2]*invB, o[jb][3]*invB);
    }
}

// ---------------------------------------------------------------------------
extern "C" void kernel_launch(void* const* d_in, const int* in_sizes, int n_in,
                              void* d_out, int out_size)
{
    const float* x  = (const float*)d_in[0];
    const float* Wq = (const float*)d_in[1];
    const float* Wk = (const float*)d_in[2];
    const float* Wv = (const float*)d_in[3];
    float* out = (float*)d_out;

    prep_kernel<<<NXB + NWB, 256>>>(x, Wq, Wk, Wv);

    const int qsmem = 2 * 18432 * 2;                // 73728 B
    cudaFuncSetAttribute(qkv_mma_kernel, cudaFuncAttributeMaxDynamicSharedMemorySize, qsmem);
    dim3 g1(M_TOT/128, 3);
    qkv_mma_kernel<<<g1, 256, qsmem>>>();

    const int smem = 44544 * 2;                     // 89088 B; 2 CTAs/SM
    cudaFuncSetAttribute(attn_mma_kernel, cudaFuncAttributeMaxDynamicSharedMemorySize, smem);
    attn_mma_kernel<<<BB*64, 128, smem>>>(out);
}

// round 17
// speedup vs baseline: 1.1518x; 1.1518x over previous
#include <cuda_runtime.h>
#include <cuda_fp16.h>
#include <cstdint>
#include <cstddef>

#define BB  8
#define TT  4096
#define CC  1024
#define HSS 128
#define M_TOT (BB*TT)
#define QSTR 136   // attn strides (halves)
#define KSTR 136
#define VSTR 72
#define XS2  72    // qkv tile stride (halves), K-chunk 64

typedef unsigned long long u64;
typedef uint32_t u32;

__device__ __half g_q [BB*TT*HSS];
__device__ __half g_k [BB*TT*HSS];
__device__ __half g_vt[BB*HSS*TT];      // V transposed [b][d][t]
__device__ __half g_xh[M_TOT*CC];       // X (fp16)
__device__ __half g_wt[3*HSS*CC];       // W transposed; Wq pre-scaled by HS^-.5*log2e

// ---------------- helpers ----------------
__device__ __forceinline__ u32 pk2h(float lo, float hi){
    u32 r; asm("cvt.rn.f16x2.f32 %0, %1, %2;" : "=r"(r) : "f"(hi), "f"(lo)); return r;
}
__device__ __forceinline__ float ex2(float x){
    float r; asm("ex2.approx.f32 %0, %1;" : "=f"(r) : "f"(x)); return r;
}
__device__ __forceinline__ void mma16(float* d, const u32* a, u32 b0, u32 b1){
    asm volatile("mma.sync.aligned.m16n8k16.row.col.f32.f16.f16.f32 "
        "{%0,%1,%2,%3}, {%4,%5,%6,%7}, {%8,%9}, {%0,%1,%2,%3};"
        : "+f"(d[0]), "+f"(d[1]), "+f"(d[2]), "+f"(d[3])
        : "r"(a[0]), "r"(a[1]), "r"(a[2]), "r"(a[3]), "r"(b0), "r"(b1));
}
__device__ __forceinline__ void ldsm4(u32* r, u32 addr){
    asm volatile("ldmatrix.sync.aligned.m8n8.x4.shared.b16 {%0,%1,%2,%3}, [%4];"
        : "=r"(r[0]), "=r"(r[1]), "=r"(r[2]), "=r"(r[3]) : "r"(addr));
}
__device__ __forceinline__ u32 s2u(const void* p){
    u32 a; asm("{ .reg .u64 t; cvta.to.shared.u64 t, %1; cvt.u32.u64 %0, t; }" : "=r"(a) : "l"(p));
    return a;
}
__device__ __forceinline__ void cpa16(u32 dst, const void* src){
    asm volatile("cp.async.cg.shared.global [%0], [%1], 16;" :: "r"(dst), "l"(src) : "memory");
}
#define CP_COMMIT() asm volatile("cp.async.commit_group;" ::: "memory")
#define CP_WAIT0()  asm volatile("cp.async.wait_group 0;" ::: "memory")

// ---------------------------------------------------------------------------
// Fused prep: X -> fp16, W -> fp16 transposed (Wq pre-scaled by HS^-.5*log2e).
// ---------------------------------------------------------------------------
#define NXB (M_TOT*CC/2048)
#define NWB (3*HSS*CC/256)
__global__ __launch_bounds__(256)
void prep_kernel(const float* __restrict__ x,
                 const float* __restrict__ Wq,
                 const float* __restrict__ Wk,
                 const float* __restrict__ Wv)
{
    if (blockIdx.x < NXB) {
        const size_t i0 = ((size_t)blockIdx.x * 256 + threadIdx.x) * 8;
        float4 v0 = *(const float4*)(x + i0);
        float4 v1 = *(const float4*)(x + i0 + 4);
        uint4 u;
        u.x = pk2h(v0.x, v0.y);
        u.y = pk2h(v0.z, v0.w);
        u.z = pk2h(v1.x, v1.y);
        u.w = pk2h(v1.z, v1.w);
        *(uint4*)(g_xh + i0) = u;
    } else {
        const int idx = (blockIdx.x - NXB) * 256 + threadIdx.x;
        const int which = idx >> 17;
        const int rem   = idx & 131071;
        const int n = rem >> 10, k = rem & 1023;
        const float* W = (which==0) ? Wq : (which==1) ? Wk : Wv;
        float v = W[(size_t)k*HSS + n];
        if (which == 0) v *= 0.12751879523595898f;   // HS^-0.5 * log2(e)
        g_wt[(size_t)which*HSS*CC + (size_t)n*CC + k] = __float2half_rn(v);
    }
}

// ---------------------------------------------------------------------------
// QKV projection — unchanged (K-chunk 64, at fp16 tensor roofline).
// ---------------------------------------------------------------------------
__global__ __launch_bounds__(256, 2)
void qkv_mma_kernel()
{
    extern __shared__ __half qsm[];
    const int which = blockIdx.y;
    const __half* __restrict__ wt = g_wt + (size_t)which*HSS*CC;

    const int m0  = blockIdx.x * 128;
    const int tid = threadIdx.x;
    const int wid  = tid >> 5;
    const int lane = tid & 31;
    const int wm = wid >> 1, wn = wid & 1;
    const int g = lane >> 2, t = lane & 3;
    const int l8 = lane & 7;
    const int m0b = 32*wm;
    const int nb  = 64*wn;

    const u32 sbase = s2u(qsm);
    const u32 a_ln = 2u*(u32)((m0b + ((lane>>3)&1)*8 + l8)*XS2 + (lane>>4)*8);
    const u32 b_ln = 2u*(u32)((nb  + (lane>>4)*8 + l8)*XS2 + ((lane>>3)&1)*8);

    float o[2][8][4];
    #pragma unroll
    for (int i = 0; i < 2; i++)
        #pragma unroll
        for (int j = 0; j < 8; j++)
            #pragma unroll
            for (int q = 0; q < 4; q++) o[i][j][q] = 0.f;

    {
        #pragma unroll
        for (int l = 0; l < 4; l++) {
            int f = tid + (l<<8);
            int row = f >> 3, c = f & 7;
            u32 doff = 2u*(u32)(row*XS2 + c*8);
            cpa16(sbase + doff,           g_xh + (size_t)(m0+row)*CC + c*8);
            cpa16(sbase + 2u*9216 + doff, wt + (size_t)row*CC + c*8);
        }
        CP_COMMIT();
    }

    for (int ic = 0; ic < 16; ic++) {
        const int buf = ic & 1;
        CP_WAIT0();
        __syncthreads();
        if (ic < 15) {
            const int k0n = (ic+1) << 6;
            const u32 db = sbase + 2u*(u32)((buf^1)*18432);
            #pragma unroll
            for (int l = 0; l < 4; l++) {
                int f = tid + (l<<8);
                int row = f >> 3, c = f & 7;
                u32 doff = 2u*(u32)(row*XS2 + c*8);
                cpa16(db + doff,           g_xh + (size_t)(m0+row)*CC + k0n + c*8);
                cpa16(db + 2u*9216 + doff, wt + (size_t)row*CC + k0n + c*8);
            }
            CP_COMMIT();
        }

        const u32 bo = sbase + 2u*(u32)(buf*18432);
        const u32 xh_a = bo + a_ln;
        const u32 wt_b = bo + 2u*9216 + b_ln;

        #pragma unroll
        for (int kk = 0; kk < 4; kk++) {
            const u32 koff = (u32)(kk << 5);
            u32 ah[2][4];
            ldsm4(ah[0], xh_a + koff);
            ldsm4(ah[1], xh_a + (u32)(16*XS2*2) + koff);
            #pragma unroll
            for (int jp = 0; jp < 4; jp++) {
                u32 bw[4];
                ldsm4(bw, wt_b + (u32)(jp*(16*XS2*2)) + koff);
                mma16(o[0][2*jp],   ah[0], bw[0], bw[1]);
                mma16(o[0][2*jp+1], ah[0], bw[2], bw[3]);
                mma16(o[1][2*jp],   ah[1], bw[0], bw[1]);
                mma16(o[1][2*jp+1], ah[1], bw[2], bw[3]);
            }
        }
    }

    if (which != 2) {
        __half* __restrict__ outh = (which==0) ? g_q : g_k;
        #pragma unroll
        for (int mb = 0; mb < 2; mb++)
            #pragma unroll
            for (int h = 0; h < 2; h++) {
                const int row = m0 + m0b + 16*mb + 8*h + g;
                #pragma unroll
                for (int j = 0; j < 8; j++) {
                    u32 p = pk2h(o[mb][j][2*h+0], o[mb][j][2*h+1]);
                    *(u32*)(outh + (size_t)row*HSS + nb + 8*j + 2*t) = p;
                }
            }
    } else {
        __syncthreads();
        float* ts = (float*)qsm;
        #pragma unroll
        for (int mb = 0; mb < 2; mb++)
            #pragma unroll
            for (int h = 0; h < 2; h++) {
                const int r = m0b + 16*mb + 8*h + g;
                #pragma unroll
                for (int j = 0; j < 8; j++) {
                    const int c = nb + 8*j + 2*t;
                    ts[c*132 + r]     = o[mb][j][2*h+0];
                    ts[(c+1)*132 + r] = o[mb][j][2*h+1];
                }
            }
        __syncthreads();
        const int bb = m0 >> 12;
        const int t0 = m0 & (TT-1);
        __half* __restrict__ vt = g_vt + (size_t)bb*HSS*TT;
        #pragma unroll
        for (int l = 0; l < 16; l++) {
            int f = tid + (l<<8);
            int d = f >> 5, c4 = f & 31;
            const float* src = &ts[d*132 + (c4<<2)];
            uint2 u;
            u.x = pk2h(src[0], src[1]);
            u.y = pk2h(src[2], src[3]);
            *(uint2*)(vt + (size_t)d*TT + t0 + (c4<<2)) = u;
        }
    }
}

// ---------------------------------------------------------------------------
// fp16 banded attention (R14 structure + hoisted Q fragments): BM=64, 4 warps,
// 2 CTAs/SM, warp-level band skip.  Q fragments loaded ONCE into registers.
// smem halves: Q@0 (64x136)  K0@8704 K1@17408  V0@26112 V1@35328.  89088 B.
// ---------------------------------------------------------------------------
__global__ __launch_bounds__(128, 2)
void attn_mma_kernel(float* __restrict__ out)
{
    extern __shared__ __half hsm[];

    const int tid  = threadIdx.x;
    const int wid  = tid >> 5;
    const int lane = tid & 31;
    const int g = lane >> 2, t = lane & 3;
    const int l8 = lane & 7;
    const int m0b = 16*wid;

    const int b  = blockIdx.x & 7;
    const int qt = 63 - (blockIdx.x >> 3);
    const int r0 = qt << 6;

    const u32 sbase = s2u(hsm);
    const u32 qa = sbase + 2u*(u32)((m0b + ((lane>>3)&1)*8 + l8)*QSTR + (lane>>4)*8);
    const u32 k_ln = 2u*(u32)((((lane>>4)*8) + l8)*KSTR + ((lane>>3)&1)*8);
    const u32 v_ln = 2u*(u32)((((lane>>4)*8) + l8)*VSTR + ((lane>>3)&1)*8);

    const __half* __restrict__ kbase  = g_k  + (size_t)b*TT*HSS;
    const __half* __restrict__ vtbase = g_vt + (size_t)b*HSS*TT;
    const __half* __restrict__ qb     = g_q  + ((size_t)b*TT + r0)*HSS;

    const int rmax = r0 + 63;
    const int ct0 = (2047 - (rmax>>1)) >> 6;
    const int ct1 = (2047 + ((rmax+1)>>1)) >> 6;

    // prologue: Q + first K + first V^T
    {
        #pragma unroll
        for (int l = 0; l < 8; l++) {
            int f = tid + (l<<7);
            int row = f >> 4, c16 = f & 15;
            cpa16(sbase + 2u*(u32)(row*QSTR + (c16<<3)), qb + row*HSS + (c16<<3));
        }
        const int c0 = ct0 << 6;
        const __half* kb = kbase + (size_t)c0*HSS;
        #pragma unroll
        for (int l = 0; l < 8; l++) {
            int f = tid + (l<<7);
            int row = f >> 4, c16 = f & 15;
            cpa16(sbase + 2u*(u32)(8704 + row*KSTR + (c16<<3)), kb + row*HSS + (c16<<3));
        }
        #pragma unroll
        for (int l = 0; l < 8; l++) {
            int f = tid + (l<<7);
            int row = f >> 3, c8 = f & 7;
            cpa16(sbase + 2u*(u32)(26112 + row*VSTR + (c8<<3)),
                  vtbase + (size_t)row*TT + c0 + (c8<<3));
        }
        CP_COMMIT();
    }

    const int grA = r0 + m0b + g, grB = grA + 8;
    const int loA = 2047 - (grA >> 1), hiA = 2047 + ((grA + 1) >> 1);
    const int loB = 2047 - (grB >> 1), hiB = 2047 + ((grB + 1) >> 1);
    const int rwn = r0 + m0b;
    const int loWn = 2047 - (rwn >> 1), hiWn = 2047 + ((rwn + 1) >> 1);
    const int rww = r0 + m0b + 15;
    const int loWw = 2047 - (rww >> 1), hiWw = 2047 + ((rww + 1) >> 1);

    // ---- hoist Q fragments: loop-invariant, load ONCE ----
    CP_WAIT0();
    __syncthreads();
    u32 aQ[8][4];
    #pragma unroll
    for (int kk = 0; kk < 8; kk++)
        ldsm4(aQ[kk], qa + (u32)(kk<<5));

    float o[16][4];
    #pragma unroll
    for (int j = 0; j < 16; j++)
        #pragma unroll
        for (int q = 0; q < 4; q++) o[j][q] = 0.f;
    float lA = 0.f, lB = 0.f;

    int buf = 0;
    for (int ct = ct0; ct <= ct1; ct++, buf ^= 1) {
        CP_WAIT0();
        __syncthreads();

        if (ct < ct1) {
            const int c0n = (ct+1) << 6;
            const __half* kb = kbase + (size_t)c0n*HSS;
            const u32 kd = sbase + 2u*(u32)(8704 + (buf^1)*8704);
            const u32 vd = sbase + 2u*(u32)(26112 + (buf^1)*9216);
            #pragma unroll
            for (int l = 0; l < 8; l++) {
                int f = tid + (l<<7);
                int row = f >> 4, c16 = f & 15;
                cpa16(kd + 2u*(u32)(row*KSTR + (c16<<3)), kb + row*HSS + (c16<<3));
            }
            #pragma unroll
            for (int l = 0; l < 8; l++) {
                int f = tid + (l<<7);
                int row = f >> 3, c8 = f & 7;
                cpa16(vd + 2u*(u32)(row*VSTR + (c8<<3)),
                      vtbase + (size_t)row*TT + c0n + (c8<<3));
            }
            CP_COMMIT();
        }

        const int c0 = ct << 6;
        if (c0 + 63 < loWw || c0 > hiWw) continue;   // warp-level band skip

        const u32 kbuf = sbase + 2u*(u32)(8704 + buf*8704) + k_ln;
        const u32 vbuf = sbase + 2u*(u32)(26112 + buf*9216) + v_ln;

        // ---- MMA1: S(16x64 per warp) = Q @ K^T  (Q frags in registers) ----
        float s[8][4];
        #pragma unroll
        for (int j = 0; j < 8; j++)
            #pragma unroll
            for (int q = 0; q < 4; q++) s[j][q] = 0.f;

        #pragma unroll
        for (int kk = 0; kk < 8; kk++) {
            #pragma unroll
            for (int jp = 0; jp < 4; jp++) {
                u32 bk[4];
                ldsm4(bk, kbuf + (u32)(jp*(16*KSTR*2)) + (u32)(kk<<5));
                mma16(s[2*jp],   aQ[kk], bk[0], bk[1]);
                mma16(s[2*jp+1], aQ[kk], bk[2], bk[3]);
            }
        }

        // ---- mask (boundary tiles only) ----
        if (c0 < loWn || c0 + 63 > hiWn) {
            #pragma unroll
            for (int jb = 0; jb < 8; jb++) {
                const int cb = c0 + 8*jb + 2*t;
                if (cb   < loA || cb   > hiA) s[jb][0] = -1e30f;
                if (cb+1 < loA || cb+1 > hiA) s[jb][1] = -1e30f;
                if (cb   < loB || cb   > hiB) s[jb][2] = -1e30f;
                if (cb+1 < loB || cb+1 > hiB) s[jb][3] = -1e30f;
            }
        }

        // ---- fused exp (2^S) + MMA2 per 16-col k-slice ----
        #pragma unroll
        for (int jk = 0; jk < 4; jk++) {
            u32 aP[4];
            #pragma unroll
            for (int h = 0; h < 2; h++) {
                const int jb = 2*jk + h;
                float p0 = ex2(s[jb][0]);
                float p1 = ex2(s[jb][1]);
                float p2 = ex2(s[jb][2]);
                float p3 = ex2(s[jb][3]);
                lA += p0 + p1;
                lB += p2 + p3;
                aP[2*h+0] = pk2h(p0, p1);
                aP[2*h+1] = pk2h(p2, p3);
            }
            #pragma unroll
            for (int jp = 0; jp < 8; jp++) {
                u32 bv[4];
                ldsm4(bv, vbuf + (u32)(jp*(16*VSTR*2)) + (u32)(jk<<5));
                mma16(o[2*jp],   aP, bv[0], bv[1]);
                mma16(o[2*jp+1], aP, bv[2], bv[3]);
            }
        }
    }

    // ---- epilogue ----
    lA += __shfl_xor_sync(0xffffffffu, lA, 1);
    lA += __shfl_xor_sync(0xffffffffu, lA, 2);
    lB += __shfl_xor_sync(0xffffffffu, lB, 1);
    lB += __shfl_xor_sync(0xffffffffu, lB, 2);
    const float invA = 1.0f / lA;
    const float invB = 1.0f / lB;

    float* __restrict__ obA = out + ((size_t)b*TT + grA)*HSS;
    float* __restrict__ obB = out + ((size_t)b*TT + grB)*HSS;
    #pragma unroll
    for (int jb = 0; jb < 16; jb++) {
        *(float2*)&obA[8*jb + 2*t] = make_float2(o[jb][0]*invA, o[jb][1]*invA);
        *(float2*)&obB[8*jb + 2*t] = make_float2(o[jb][2]*invB, o[jb][3]*invB);
    }
}

// ---------------------------------------------------------------------------
extern "C" void kernel_launch(void* const* d_in, const int* in_sizes, int n_in,
                              void* d_out, int out_size)
{
    const float* x  = (const float*)d_in[0];
    const float* Wq = (const float*)d_in[1];
    const float* Wk = (const float*)d_in[2];
    const float* Wv = (const float*)d_in[3];
    float* out = (float*)d_out;

    prep_kernel<<<NXB + NWB, 256>>>(x, Wq, Wk, Wv);

    const int qsmem = 2 * 18432 * 2;                // 73728 B
    cudaFuncSetAttribute(qkv_mma_kernel, cudaFuncAttributeMaxDynamicSharedMemorySize, qsmem);
    dim3 g1(M_TOT/128, 3);
    qkv_mma_kernel<<<g1, 256, qsmem>>>();

    const int smem = 44544 * 2;                     // 89088 B; 2 CTAs/SM
    cudaFuncSetAttribute(attn_mma_kernel, cudaFuncAttributeMaxDynamicSharedMemorySize, smem);
    attn_mma_kernel<<<BB*64, 128, smem>>>(out);
}